// round 16
// baseline (speedup 1.0000x reference)
#include <cuda_runtime.h>
#include <math.h>
#include <stdint.h>

// ---------------- problem constants ----------------
#define S_TOT   20197
#define BATCH   2
#define T_TOT   40394          // BATCH * S_TOT
#define DMODEL  256
#define NHEAD   8
#define HDIM    32
#define NLEV    4
#define NPNT    4
#define DFF     1024
#define NLAYERS 6

// level geometry
__device__ __forceinline__ void level_consts(int l, int& H, int& W, int& start) {
    const int Hs[4] = {100, 50, 25, 13};
    const int Ws[4] = {152, 76, 38, 19};
    const int St[4] = {0, 15200, 19000, 19950};
    H = Hs[l]; W = Ws[l]; start = St[l];
}

// ---------------- scratch (static device memory, no allocs) ----------------
__device__ float g_value[(size_t)T_TOT * DMODEL];
__device__ float g_q    [(size_t)T_TOT * DMODEL];
__device__ float g_off  [(size_t)T_TOT * DMODEL];
__device__ float g_attn [(size_t)T_TOT * (NHEAD * NLEV * NPNT)];
__device__ float g_acc  [(size_t)T_TOT * DMODEL];
__device__ float g_a    [(size_t)T_TOT * DMODEL];
__device__ float g_ff   [(size_t)T_TOT * DFF];
__device__ float g_cur  [(size_t)T_TOT * DMODEL];
__device__ float g_ref  [(size_t)T_TOT * NLEV * 2];

// ================= helpers ==========================
__device__ __forceinline__ uint32_t smem_u32(const void* p) {
    uint32_t a;
    asm("{ .reg .u64 t; cvta.to.shared.u64 t, %1; cvt.u32.u64 %0, t; }"
        : "=r"(a) : "l"(p));
    return a;
}

__device__ __forceinline__ void mma_16n8k8(float* d,
    uint32_t a0, uint32_t a1, uint32_t a2, uint32_t a3,
    uint32_t b0, uint32_t b1)
{
    asm volatile(
        "mma.sync.aligned.m16n8k8.row.col.f32.tf32.tf32.f32 "
        "{%0,%1,%2,%3}, {%4,%5,%6,%7}, {%8,%9}, {%0,%1,%2,%3};"
        : "+f"(d[0]), "+f"(d[1]), "+f"(d[2]), "+f"(d[3])
        : "r"(a0), "r"(a1), "r"(a2), "r"(a3), "r"(b0), "r"(b1));
}

#define CP_ASYNC_16(dst, src, sz) \
    asm volatile("cp.async.cg.shared.global [%0], [%1], 16, %2;" \
        :: "r"(dst), "l"(src), "r"(sz) : "memory")
#define CP_COMMIT() asm volatile("cp.async.commit_group;" ::: "memory")
#define CP_WAIT(n)  asm volatile("cp.async.wait_group %0;" :: "n"(n) : "memory")

// ================= cp.async pipelined mma.sync tf32 GEMM ===================
// (R14 configuration — known good: 54.5us @ N=256, occ ~23%)
// C[M,N] = A[M,K] @ W[K,N] + bias (optional relu).
// BM=BN=128, BK=16, 256 threads = 8 warps (2 x 4), warp tile 64x32.
// 3-stage cp.async pipeline; fp32 bits fed to tf32 MMA (HW truncation).
#define GSTAGES   3
#define A_STRIDE  20
#define B_STRIDE  132
#define STAGE_FLTS (128 * A_STRIDE + 16 * B_STRIDE)   // 4672
#define GEMM_SMEM (GSTAGES * STAGE_FLTS * 4)          // 56064 bytes

__global__ __launch_bounds__(256) void gemm_tf32(
    const float* __restrict__ A, const float* __restrict__ W,
    const float* __restrict__ bias, float* __restrict__ C,
    int M, int N, int K, int relu)
{
    extern __shared__ float sm[];
    const int tid   = threadIdx.x;
    const int lane  = tid & 31;
    const int wid   = tid >> 5;
    const int warpM = wid & 1;          // 0..1 -> M offset 0/64
    const int warpN = wid >> 1;         // 0..3 -> N offset 0/32/64/96
    const int m0 = blockIdx.y * 128;
    const int n0 = blockIdx.x * 128;
    const int qr = lane >> 2;           // 0..7
    const int qc = lane & 3;            // 0..3

    const uint32_t smBase = smem_u32(sm);

    // cp.async indices: 256 threads move A(128x16) and B(16x128), 2 chunks each
    const int aRow0 = tid >> 2;          // 0..63 (+64)
    const int aC4   = (tid & 3) << 2;    // 0,4,8,12
    const int bK0   = tid >> 5;          // 0..7 (+8)
    const int bN4   = (tid & 31) << 2;   // 0..124

    float acc[4][4][4];
    #pragma unroll
    for (int i = 0; i < 4; i++)
        #pragma unroll
        for (int j = 0; j < 4; j++)
            #pragma unroll
            for (int k = 0; k < 4; k++) acc[i][j][k] = 0.f;

    const int nChunks = K >> 4;

    auto issue = [&](int c) {
        const int st = c % GSTAGES;
        const int k0 = c << 4;
        const uint32_t aBase = smBase + (uint32_t)(st * STAGE_FLTS) * 4u;
        const uint32_t bBase = aBase + 128u * A_STRIDE * 4u;
        #pragma unroll
        for (int i = 0; i < 2; i++) {
            int row = aRow0 + i * 64;
            int gr  = m0 + row;
            int sz  = (gr < M) ? 16 : 0;
            int grc = gr < M ? gr : (M - 1);
            const float* src = A + (size_t)grc * K + k0 + aC4;
            uint32_t dst = aBase + (uint32_t)(row * A_STRIDE + aC4) * 4u;
            CP_ASYNC_16(dst, src, sz);
        }
        #pragma unroll
        for (int i = 0; i < 2; i++) {
            int k = bK0 + i * 8;
            const float* src = W + (size_t)(k0 + k) * N + n0 + bN4;
            uint32_t dst = bBase + (uint32_t)(k * B_STRIDE + bN4) * 4u;
            CP_ASYNC_16(dst, src, 16);
        }
        CP_COMMIT();
    };

    issue(0);
    if (nChunks > 1) issue(1);

    for (int c = 0; c < nChunks; c++) {
        if (c + 1 < nChunks) { CP_WAIT(1); } else { CP_WAIT(0); }
        __syncthreads();
        if (c + 2 < nChunks) issue(c + 2);

        const int st = c % GSTAGES;
        const float* As_ = sm + st * STAGE_FLTS;
        const float* Bs_ = As_ + 128 * A_STRIDE;

        #pragma unroll
        for (int s = 0; s < 2; s++) {
            const int ka  = qc + s * 8;
            const int ka2 = ka + 4;
            uint32_t af[4][4];
            #pragma unroll
            for (int mt = 0; mt < 4; mt++) {
                int r = warpM * 64 + mt * 16 + qr;
                af[mt][0] = __float_as_uint(As_[r * A_STRIDE + ka]);
                af[mt][1] = __float_as_uint(As_[(r + 8) * A_STRIDE + ka]);
                af[mt][2] = __float_as_uint(As_[r * A_STRIDE + ka2]);
                af[mt][3] = __float_as_uint(As_[(r + 8) * A_STRIDE + ka2]);
            }
            uint32_t bfr[4][2];
            #pragma unroll
            for (int nt = 0; nt < 4; nt++) {
                int n = warpN * 32 + nt * 8 + qr;
                bfr[nt][0] = __float_as_uint(Bs_[ka  * B_STRIDE + n]);
                bfr[nt][1] = __float_as_uint(Bs_[ka2 * B_STRIDE + n]);
            }
            #pragma unroll
            for (int mt = 0; mt < 4; mt++)
                #pragma unroll
                for (int nt = 0; nt < 4; nt++)
                    mma_16n8k8(acc[mt][nt],
                               af[mt][0], af[mt][1], af[mt][2], af[mt][3],
                               bfr[nt][0], bfr[nt][1]);
        }
    }

    // ---- epilogue: bias + optional relu ----
    #pragma unroll
    for (int nt = 0; nt < 4; nt++) {
        int col = n0 + warpN * 32 + nt * 8 + qc * 2;
        float b0 = bias[col], b1 = bias[col + 1];
        #pragma unroll
        for (int mt = 0; mt < 4; mt++) {
            int row = m0 + warpM * 64 + mt * 16 + qr;
            float2 lo = make_float2(acc[mt][nt][0] + b0, acc[mt][nt][1] + b1);
            float2 hi = make_float2(acc[mt][nt][2] + b0, acc[mt][nt][3] + b1);
            if (relu) {
                lo.x = fmaxf(lo.x, 0.f); lo.y = fmaxf(lo.y, 0.f);
                hi.x = fmaxf(hi.x, 0.f); hi.y = fmaxf(hi.y, 0.f);
            }
            if (row < M)     *(float2*)(C + (size_t)row * N + col)       = lo;
            if (row + 8 < M) *(float2*)(C + (size_t)(row + 8) * N + col) = hi;
        }
    }
}

// ---------------- elementwise add: q = cur + pos ----------------
__global__ void ew_add(const float* __restrict__ x, const float* __restrict__ y,
                       float* __restrict__ out, int n)
{
    int i = blockIdx.x * blockDim.x + threadIdx.x;
    if (i < n) out[i] = x[i] + y[i];
}

// ---------------- reference points ----------------
__global__ void compute_ref(const float* __restrict__ vr, float* __restrict__ ref)
{
    int t = blockIdx.x * blockDim.x + threadIdx.x;
    if (t >= T_TOT) return;
    int b = t / S_TOT;
    int s = t - b * S_TOT;

    int lq, rem;
    if      (s >= 19950) { lq = 3; rem = s - 19950; }
    else if (s >= 19000) { lq = 2; rem = s - 19000; }
    else if (s >= 15200) { lq = 1; rem = s - 15200; }
    else                 { lq = 0; rem = s; }

    int H, W, st;
    level_consts(lq, H, W, st);
    int iy = rem / W;
    int ix = rem - iy * W;

    const float* v = vr + b * (NLEV * 2);
    float rx = (ix + 0.5f) / (v[lq * 2 + 0] * (float)W);
    float ry = (iy + 0.5f) / (v[lq * 2 + 1] * (float)H);

    #pragma unroll
    for (int l = 0; l < 4; l++) {
        ref[(size_t)t * 8 + l * 2 + 0] = rx * v[l * 2 + 0];
        ref[(size_t)t * 8 + l * 2 + 1] = ry * v[l * 2 + 1];
    }
}

// ---------------- MSDA bilinear sampling (softmax fused, 4 tokens/block) ----
// block = 256 threads = 8 warps = 8 heads; each warp loops over 4 consecutive
// tokens (adjacent tokens sample overlapping value lines -> L1 reuse).
#define TOK_PER_BLK 4

__global__ __launch_bounds__(256) void msda_sample(
    const float* __restrict__ value, const float* __restrict__ off,
    const float* __restrict__ logits, const float* __restrict__ ref,
    float* __restrict__ acc)
{
    const int t0 = blockIdx.x * TOK_PER_BLK;
    const int h = threadIdx.x >> 5;
    const int d = threadIdx.x & 31;
    const int hd = h * HDIM + d;

    #pragma unroll
    for (int it = 0; it < TOK_PER_BLK; it++) {
        const int t = t0 + it;
        if (t >= T_TOT) break;
        const int b = (t >= S_TOT) ? 1 : 0;

        // ---- warp softmax over the 16 logits of (t, h); weights via shuffle ----
        const float* lp = logits + (size_t)t * 128 + h * 16;
        float lg = (d < 16) ? lp[d] : -1e30f;
        float mx = lg;
        #pragma unroll
        for (int o = 8; o > 0; o >>= 1) mx = fmaxf(mx, __shfl_xor_sync(0xFFFFFFFFu, mx, o));
        float e = (d < 16) ? expf(lg - mx) : 0.f;
        float ssum = e;
        #pragma unroll
        for (int o = 8; o > 0; o >>= 1) ssum += __shfl_xor_sync(0xFFFFFFFFu, ssum, o);
        const float myw = e / ssum;       // valid in lanes 0..15

        const float* vb = value + (size_t)b * S_TOT * DMODEL;
        const float* rp = ref  + (size_t)t * 8;
        const float* op = off  + (size_t)t * DMODEL + h * 32;

        float a = 0.f;
        #pragma unroll
        for (int l = 0; l < 4; l++) {
            int Hl, Wl, st;
            level_consts(l, Hl, Wl, st);
            const float* vlev = vb + (size_t)st * DMODEL;
            float rx = rp[l * 2], ry = rp[l * 2 + 1];
            float invW = 1.f / (float)Wl, invH = 1.f / (float)Hl;
            #pragma unroll
            for (int p = 0; p < 4; p++) {
                float ox = op[l * 8 + p * 2], oy = op[l * 8 + p * 2 + 1];
                float w  = __shfl_sync(0xFFFFFFFFu, myw, l * 4 + p);
                float lx = rx + ox * invW;
                float ly = ry + oy * invH;
                float px = lx * (float)Wl - 0.5f;
                float py = ly * (float)Hl - 0.5f;
                float fx = floorf(px), fy = floorf(py);
                float dx = px - fx, dy = py - fy;
                int x0 = (int)fx, y0 = (int)fy;
                int x1 = x0 + 1, y1 = y0 + 1;
                bool vx0 = (x0 >= 0) & (x0 < Wl), vx1 = (x1 >= 0) & (x1 < Wl);
                bool vy0 = (y0 >= 0) & (y0 < Hl), vy1 = (y1 >= 0) & (y1 < Hl);
                int cx0 = min(max(x0, 0), Wl - 1), cx1 = min(max(x1, 0), Wl - 1);
                int cy0 = min(max(y0, 0), Hl - 1), cy1 = min(max(y1, 0), Hl - 1);
                float w00 = (vx0 && vy0) ? (1.f - dx) * (1.f - dy) : 0.f;
                float w10 = (vx1 && vy0) ? dx * (1.f - dy) : 0.f;
                float w01 = (vx0 && vy1) ? (1.f - dx) * dy : 0.f;
                float w11 = (vx1 && vy1) ? dx * dy : 0.f;
                float v00 = vlev[(size_t)(cy0 * Wl + cx0) * DMODEL + hd];
                float v10 = vlev[(size_t)(cy0 * Wl + cx1) * DMODEL + hd];
                float v01 = vlev[(size_t)(cy1 * Wl + cx0) * DMODEL + hd];
                float v11 = vlev[(size_t)(cy1 * Wl + cx1) * DMODEL + hd];
                float s = v00 * w00 + v10 * w10 + v01 * w01 + v11 * w11;
                a = fmaf(w, s, a);
            }
        }
        acc[(size_t)t * DMODEL + hd] = a;
    }
}

// ---------------- residual add + layernorm (row = 256) ----------------
__global__ __launch_bounds__(256) void add_ln(
    const float* __restrict__ x, const float* __restrict__ r,
    const float* __restrict__ g, const float* __restrict__ bta,
    float* __restrict__ out)
{
    __shared__ float warpsum[8];
    __shared__ float bcast;
    const int row = blockIdx.x, tid = threadIdx.x;
    const int lane = tid & 31, wid = tid >> 5;

    float v = x[(size_t)row * 256 + tid] + r[(size_t)row * 256 + tid];

    float s = v;
    #pragma unroll
    for (int o = 16; o > 0; o >>= 1) s += __shfl_xor_sync(0xFFFFFFFFu, s, o);
    if (lane == 0) warpsum[wid] = s;
    __syncthreads();
    if (tid == 0) {
        float tt = 0.f;
        #pragma unroll
        for (int i = 0; i < 8; i++) tt += warpsum[i];
        bcast = tt * (1.f / 256.f);
    }
    __syncthreads();
    float mean = bcast;
    float dcen = v - mean;

    float s2 = dcen * dcen;
    #pragma unroll
    for (int o = 16; o > 0; o >>= 1) s2 += __shfl_xor_sync(0xFFFFFFFFu, s2, o);
    if (lane == 0) warpsum[wid] = s2;
    __syncthreads();
    if (tid == 0) {
        float tt = 0.f;
        #pragma unroll
        for (int i = 0; i < 8; i++) tt += warpsum[i];
        bcast = tt * (1.f / 256.f);
    }
    __syncthreads();
    float var = bcast;

    out[(size_t)row * 256 + tid] = dcen * rsqrtf(var + 1e-5f) * g[tid] + bta[tid];
}

// ---------------- host orchestration ----------------
static inline void run_gemm(const float* A, const float* W, const float* bias,
                            float* C, int M, int N, int K, int relu)
{
    dim3 grid(N / 128, (M + 127) / 128);
    gemm_tf32<<<grid, 256, GEMM_SMEM>>>(A, W, bias, C, M, N, K, relu);
}

extern "C" void kernel_launch(void* const* d_in, const int* in_sizes, int n_in,
                              void* d_out, int out_size)
{
    const float* src     = (const float*)d_in[0];
    const float* pos     = (const float*)d_in[1];
    const float* vratios = (const float*)d_in[2];
    const float* W_value = (const float*)d_in[3];
    const float* b_value = (const float*)d_in[4];
    const float* W_off   = (const float*)d_in[5];
    const float* b_off   = (const float*)d_in[6];
    const float* W_attn  = (const float*)d_in[7];
    const float* b_attn  = (const float*)d_in[8];
    const float* W_out   = (const float*)d_in[9];
    const float* b_out   = (const float*)d_in[10];
    const float* ln1g    = (const float*)d_in[11];
    const float* ln1b    = (const float*)d_in[12];
    const float* W_ff1   = (const float*)d_in[13];
    const float* b_ff1   = (const float*)d_in[14];
    const float* W_ff2   = (const float*)d_in[15];
    const float* b_ff2   = (const float*)d_in[16];
    const float* ln2g    = (const float*)d_in[17];
    const float* ln2b    = (const float*)d_in[18];

    cudaFuncSetAttribute(gemm_tf32, cudaFuncAttributeMaxDynamicSharedMemorySize,
                         GEMM_SMEM);

    float *pval, *pq, *poff, *pattn, *pacc, *pa, *pff, *pcur, *pref;
    cudaGetSymbolAddress((void**)&pval,  g_value);
    cudaGetSymbolAddress((void**)&pq,    g_q);
    cudaGetSymbolAddress((void**)&poff,  g_off);
    cudaGetSymbolAddress((void**)&pattn, g_attn);
    cudaGetSymbolAddress((void**)&pacc,  g_acc);
    cudaGetSymbolAddress((void**)&pa,    g_a);
    cudaGetSymbolAddress((void**)&pff,   g_ff);
    cudaGetSymbolAddress((void**)&pcur,  g_cur);
    cudaGetSymbolAddress((void**)&pref,  g_ref);

    const int nElem = T_TOT * DMODEL;
    const int M = T_TOT;

    compute_ref<<<(T_TOT + 255) / 256, 256>>>(vratios, pref);

    const float* cur = src;
    for (int i = 0; i < NLAYERS; i++) {
        const float* Wv  = W_value + (size_t)i * DMODEL * DMODEL;
        const float* bv  = b_value + (size_t)i * DMODEL;
        const float* Wof = W_off   + (size_t)i * DMODEL * DMODEL;
        const float* bof = b_off   + (size_t)i * DMODEL;
        const float* Wat = W_attn  + (size_t)i * DMODEL * 128;
        const float* bat = b_attn  + (size_t)i * 128;
        const float* Wo  = W_out   + (size_t)i * DMODEL * DMODEL;
        const float* bo  = b_out   + (size_t)i * DMODEL;
        const float* Wf1 = W_ff1   + (size_t)i * DMODEL * DFF;
        const float* bf1 = b_ff1   + (size_t)i * DFF;
        const float* Wf2 = W_ff2   + (size_t)i * DFF * DMODEL;
        const float* bf2 = b_ff2   + (size_t)i * DMODEL;

        // value projection
        run_gemm(cur, Wv, bv, pval, M, DMODEL, DMODEL, 0);
        // q = cur + pos
        ew_add<<<(nElem + 255) / 256, 256>>>(cur, pos, pq, nElem);
        // offsets / attention logits
        run_gemm(pq, Wof, bof, poff, M, DMODEL, DMODEL, 0);
        run_gemm(pq, Wat, bat, pattn, M, 128, DMODEL, 0);
        // deformable sampling (softmax fused)
        msda_sample<<<(T_TOT + TOK_PER_BLK - 1) / TOK_PER_BLK, 256>>>(
            pval, poff, pattn, pref, pacc);
        // output projection + residual LN
        run_gemm(pacc, Wo, bo, pa, M, DMODEL, DMODEL, 0);
        add_ln<<<T_TOT, 256>>>(cur, pa, ln1g + (size_t)i * DMODEL,
                               ln1b + (size_t)i * DMODEL, pcur);
        // FFN
        run_gemm(pcur, Wf1, bf1, pff, M, DFF, DMODEL, 1);
        run_gemm(pff, Wf2, bf2, pa, M, DMODEL, DFF, 0);
        float* dst = (i == NLAYERS - 1) ? (float*)d_out : pcur;
        add_ln<<<T_TOT, 256>>>(pcur, pa, ln2g + (size_t)i * DMODEL,
                               ln2b + (size_t)i * DMODEL, dst);
        cur = pcur;
    }
}

// round 17
// speedup vs baseline: 1.0591x; 1.0591x over previous
#include <cuda_runtime.h>
#include <cuda_fp16.h>
#include <math.h>
#include <stdint.h>

// ---------------- problem constants ----------------
#define S_TOT   20197
#define BATCH   2
#define T_TOT   40394          // BATCH * S_TOT
#define DMODEL  256
#define NHEAD   8
#define HDIM    32
#define NLEV    4
#define NPNT    4
#define DFF     1024
#define NLAYERS 6

// level geometry
__device__ __forceinline__ void level_consts(int l, int& H, int& W, int& start) {
    const int Hs[4] = {100, 50, 25, 13};
    const int Ws[4] = {152, 76, 38, 19};
    const int St[4] = {0, 15200, 19000, 19950};
    H = Hs[l]; W = Ws[l]; start = St[l];
}

// ---------------- scratch (static device memory, no allocs) ----------------
__device__ __half g_value_h[(size_t)T_TOT * DMODEL];
__device__ float g_q    [(size_t)T_TOT * DMODEL];
__device__ float g_off  [(size_t)T_TOT * DMODEL];
__device__ float g_attn [(size_t)T_TOT * (NHEAD * NLEV * NPNT)];
__device__ float g_acc  [(size_t)T_TOT * DMODEL];
__device__ float g_a    [(size_t)T_TOT * DMODEL];
__device__ float g_ff   [(size_t)T_TOT * DFF];
__device__ float g_cur  [(size_t)T_TOT * DMODEL];
__device__ float g_ref  [(size_t)T_TOT * NLEV * 2];

// ================= helpers ==========================
__device__ __forceinline__ uint32_t smem_u32(const void* p) {
    uint32_t a;
    asm("{ .reg .u64 t; cvta.to.shared.u64 t, %1; cvt.u32.u64 %0, t; }"
        : "=r"(a) : "l"(p));
    return a;
}

__device__ __forceinline__ void mma_16n8k8(float* d,
    uint32_t a0, uint32_t a1, uint32_t a2, uint32_t a3,
    uint32_t b0, uint32_t b1)
{
    asm volatile(
        "mma.sync.aligned.m16n8k8.row.col.f32.tf32.tf32.f32 "
        "{%0,%1,%2,%3}, {%4,%5,%6,%7}, {%8,%9}, {%0,%1,%2,%3};"
        : "+f"(d[0]), "+f"(d[1]), "+f"(d[2]), "+f"(d[3])
        : "r"(a0), "r"(a1), "r"(a2), "r"(a3), "r"(b0), "r"(b1));
}

#define CP_ASYNC_16(dst, src, sz) \
    asm volatile("cp.async.cg.shared.global [%0], [%1], 16, %2;" \
        :: "r"(dst), "l"(src), "r"(sz) : "memory")
#define CP_COMMIT() asm volatile("cp.async.commit_group;" ::: "memory")
#define CP_WAIT(n)  asm volatile("cp.async.wait_group %0;" :: "n"(n) : "memory")

// ================= cp.async pipelined mma.sync tf32 GEMM ===================
// (R14 configuration — known good: ~54us @ N=256, occ ~23%)
// C[M,N] = A[M,K] @ W[K,N] + bias.
// mode: 0 = f32 out, 1 = f32 out + relu, 2 = f16 out
// BM=BN=128, BK=16, 256 threads = 8 warps (2 x 4), warp tile 64x32.
#define GSTAGES   3
#define A_STRIDE  20
#define B_STRIDE  132
#define STAGE_FLTS (128 * A_STRIDE + 16 * B_STRIDE)   // 4672
#define GEMM_SMEM (GSTAGES * STAGE_FLTS * 4)          // 56064 bytes

__global__ __launch_bounds__(256) void gemm_tf32(
    const float* __restrict__ A, const float* __restrict__ W,
    const float* __restrict__ bias, void* __restrict__ Cv,
    int M, int N, int K, int mode)
{
    extern __shared__ float sm[];
    const int tid   = threadIdx.x;
    const int lane  = tid & 31;
    const int wid   = tid >> 5;
    const int warpM = wid & 1;          // 0..1 -> M offset 0/64
    const int warpN = wid >> 1;         // 0..3 -> N offset 0/32/64/96
    const int m0 = blockIdx.y * 128;
    const int n0 = blockIdx.x * 128;
    const int qr = lane >> 2;           // 0..7
    const int qc = lane & 3;            // 0..3

    const uint32_t smBase = smem_u32(sm);

    // cp.async indices: 256 threads move A(128x16) and B(16x128), 2 chunks each
    const int aRow0 = tid >> 2;          // 0..63 (+64)
    const int aC4   = (tid & 3) << 2;    // 0,4,8,12
    const int bK0   = tid >> 5;          // 0..7 (+8)
    const int bN4   = (tid & 31) << 2;   // 0..124

    float acc[4][4][4];
    #pragma unroll
    for (int i = 0; i < 4; i++)
        #pragma unroll
        for (int j = 0; j < 4; j++)
            #pragma unroll
            for (int k = 0; k < 4; k++) acc[i][j][k] = 0.f;

    const int nChunks = K >> 4;

    auto issue = [&](int c) {
        const int st = c % GSTAGES;
        const int k0 = c << 4;
        const uint32_t aBase = smBase + (uint32_t)(st * STAGE_FLTS) * 4u;
        const uint32_t bBase = aBase + 128u * A_STRIDE * 4u;
        #pragma unroll
        for (int i = 0; i < 2; i++) {
            int row = aRow0 + i * 64;
            int gr  = m0 + row;
            int sz  = (gr < M) ? 16 : 0;
            int grc = gr < M ? gr : (M - 1);
            const float* src = A + (size_t)grc * K + k0 + aC4;
            uint32_t dst = aBase + (uint32_t)(row * A_STRIDE + aC4) * 4u;
            CP_ASYNC_16(dst, src, sz);
        }
        #pragma unroll
        for (int i = 0; i < 2; i++) {
            int k = bK0 + i * 8;
            const float* src = W + (size_t)(k0 + k) * N + n0 + bN4;
            uint32_t dst = bBase + (uint32_t)(k * B_STRIDE + bN4) * 4u;
            CP_ASYNC_16(dst, src, 16);
        }
        CP_COMMIT();
    };

    issue(0);
    if (nChunks > 1) issue(1);

    for (int c = 0; c < nChunks; c++) {
        if (c + 1 < nChunks) { CP_WAIT(1); } else { CP_WAIT(0); }
        __syncthreads();
        if (c + 2 < nChunks) issue(c + 2);

        const int st = c % GSTAGES;
        const float* As_ = sm + st * STAGE_FLTS;
        const float* Bs_ = As_ + 128 * A_STRIDE;

        #pragma unroll
        for (int s = 0; s < 2; s++) {
            const int ka  = qc + s * 8;
            const int ka2 = ka + 4;
            uint32_t af[4][4];
            #pragma unroll
            for (int mt = 0; mt < 4; mt++) {
                int r = warpM * 64 + mt * 16 + qr;
                af[mt][0] = __float_as_uint(As_[r * A_STRIDE + ka]);
                af[mt][1] = __float_as_uint(As_[(r + 8) * A_STRIDE + ka]);
                af[mt][2] = __float_as_uint(As_[r * A_STRIDE + ka2]);
                af[mt][3] = __float_as_uint(As_[(r + 8) * A_STRIDE + ka2]);
            }
            uint32_t bfr[4][2];
            #pragma unroll
            for (int nt = 0; nt < 4; nt++) {
                int n = warpN * 32 + nt * 8 + qr;
                bfr[nt][0] = __float_as_uint(Bs_[ka  * B_STRIDE + n]);
                bfr[nt][1] = __float_as_uint(Bs_[ka2 * B_STRIDE + n]);
            }
            #pragma unroll
            for (int mt = 0; mt < 4; mt++)
                #pragma unroll
                for (int nt = 0; nt < 4; nt++)
                    mma_16n8k8(acc[mt][nt],
                               af[mt][0], af[mt][1], af[mt][2], af[mt][3],
                               bfr[nt][0], bfr[nt][1]);
        }
    }

    // ---- epilogue: bias (+ relu / f16 store) ----
    #pragma unroll
    for (int nt = 0; nt < 4; nt++) {
        int col = n0 + warpN * 32 + nt * 8 + qc * 2;
        float b0 = bias[col], b1 = bias[col + 1];
        #pragma unroll
        for (int mt = 0; mt < 4; mt++) {
            int row = m0 + warpM * 64 + mt * 16 + qr;
            float2 lo = make_float2(acc[mt][nt][0] + b0, acc[mt][nt][1] + b1);
            float2 hi = make_float2(acc[mt][nt][2] + b0, acc[mt][nt][3] + b1);
            if (mode == 1) {
                lo.x = fmaxf(lo.x, 0.f); lo.y = fmaxf(lo.y, 0.f);
                hi.x = fmaxf(hi.x, 0.f); hi.y = fmaxf(hi.y, 0.f);
            }
            if (mode == 2) {
                __half2* Ch = (__half2*)Cv;
                if (row < M)
                    Ch[((size_t)row * N + col) >> 1] = __floats2half2_rn(lo.x, lo.y);
                if (row + 8 < M)
                    Ch[((size_t)(row + 8) * N + col) >> 1] = __floats2half2_rn(hi.x, hi.y);
            } else {
                float* C = (float*)Cv;
                if (row < M)     *(float2*)(C + (size_t)row * N + col)       = lo;
                if (row + 8 < M) *(float2*)(C + (size_t)(row + 8) * N + col) = hi;
            }
        }
    }
}

// ---------------- elementwise add: q = cur + pos ----------------
__global__ void ew_add(const float* __restrict__ x, const float* __restrict__ y,
                       float* __restrict__ out, int n)
{
    int i = blockIdx.x * blockDim.x + threadIdx.x;
    if (i < n) out[i] = x[i] + y[i];
}

// ---------------- reference points ----------------
__global__ void compute_ref(const float* __restrict__ vr, float* __restrict__ ref)
{
    int t = blockIdx.x * blockDim.x + threadIdx.x;
    if (t >= T_TOT) return;
    int b = t / S_TOT;
    int s = t - b * S_TOT;

    int lq, rem;
    if      (s >= 19950) { lq = 3; rem = s - 19950; }
    else if (s >= 19000) { lq = 2; rem = s - 19000; }
    else if (s >= 15200) { lq = 1; rem = s - 15200; }
    else                 { lq = 0; rem = s; }

    int H, W, st;
    level_consts(lq, H, W, st);
    int iy = rem / W;
    int ix = rem - iy * W;

    const float* v = vr + b * (NLEV * 2);
    float rx = (ix + 0.5f) / (v[lq * 2 + 0] * (float)W);
    float ry = (iy + 0.5f) / (v[lq * 2 + 1] * (float)H);

    #pragma unroll
    for (int l = 0; l < 4; l++) {
        ref[(size_t)t * 8 + l * 2 + 0] = rx * v[l * 2 + 0];
        ref[(size_t)t * 8 + l * 2 + 1] = ry * v[l * 2 + 1];
    }
}

// ---------------- MSDA bilinear sampling (softmax fused, f16 value) --------
// one block per token; warp = head; lane = head-dim (R14 structure)
__global__ __launch_bounds__(256) void msda_sample(
    const __half* __restrict__ value, const float* __restrict__ off,
    const float* __restrict__ logits, const float* __restrict__ ref,
    float* __restrict__ acc)
{
    __shared__ float sw[NHEAD][16];
    const int t = blockIdx.x;
    const int h = threadIdx.x >> 5;
    const int d = threadIdx.x & 31;
    const int b = (t >= S_TOT) ? 1 : 0;

    // ---- warp softmax over the 16 attention logits of this (token, head) ----
    {
        const float* lp = logits + (size_t)t * 128 + h * 16;
        float lg = (d < 16) ? lp[d] : -1e30f;
        float mx = lg;
        #pragma unroll
        for (int o = 8; o > 0; o >>= 1) mx = fmaxf(mx, __shfl_xor_sync(0xFFFFFFFFu, mx, o));
        float e = (d < 16) ? expf(lg - mx) : 0.f;
        float s = e;
        #pragma unroll
        for (int o = 8; o > 0; o >>= 1) s += __shfl_xor_sync(0xFFFFFFFFu, s, o);
        if (d < 16) sw[h][d] = e / s;
        __syncwarp();
    }

    const __half* vb = value + (size_t)b * S_TOT * DMODEL;
    const float* rp = ref  + (size_t)t * 8;
    const float* op = off  + (size_t)t * DMODEL + h * 32;
    const int hd = h * HDIM + d;

    float a = 0.f;
    #pragma unroll
    for (int l = 0; l < 4; l++) {
        int Hl, Wl, st;
        level_consts(l, Hl, Wl, st);
        const __half* vlev = vb + (size_t)st * DMODEL;
        float rx = rp[l * 2], ry = rp[l * 2 + 1];
        float invW = 1.f / (float)Wl, invH = 1.f / (float)Hl;
        #pragma unroll
        for (int p = 0; p < 4; p++) {
            float ox = op[l * 8 + p * 2], oy = op[l * 8 + p * 2 + 1];
            float w  = sw[h][l * 4 + p];
            float lx = rx + ox * invW;
            float ly = ry + oy * invH;
            float px = lx * (float)Wl - 0.5f;
            float py = ly * (float)Hl - 0.5f;
            float fx = floorf(px), fy = floorf(py);
            float dx = px - fx, dy = py - fy;
            int x0 = (int)fx, y0 = (int)fy;
            int x1 = x0 + 1, y1 = y0 + 1;
            bool vx0 = (x0 >= 0) & (x0 < Wl), vx1 = (x1 >= 0) & (x1 < Wl);
            bool vy0 = (y0 >= 0) & (y0 < Hl), vy1 = (y1 >= 0) & (y1 < Hl);
            int cx0 = min(max(x0, 0), Wl - 1), cx1 = min(max(x1, 0), Wl - 1);
            int cy0 = min(max(y0, 0), Hl - 1), cy1 = min(max(y1, 0), Hl - 1);
            float w00 = (vx0 && vy0) ? (1.f - dx) * (1.f - dy) : 0.f;
            float w10 = (vx1 && vy0) ? dx * (1.f - dy) : 0.f;
            float w01 = (vx0 && vy1) ? (1.f - dx) * dy : 0.f;
            float w11 = (vx1 && vy1) ? dx * dy : 0.f;
            float v00 = __half2float(vlev[(size_t)(cy0 * Wl + cx0) * DMODEL + hd]);
            float v10 = __half2float(vlev[(size_t)(cy0 * Wl + cx1) * DMODEL + hd]);
            float v01 = __half2float(vlev[(size_t)(cy1 * Wl + cx0) * DMODEL + hd]);
            float v11 = __half2float(vlev[(size_t)(cy1 * Wl + cx1) * DMODEL + hd]);
            float s = v00 * w00 + v10 * w10 + v01 * w01 + v11 * w11;
            a = fmaf(w, s, a);
        }
    }
    acc[(size_t)t * DMODEL + hd] = a;
}

// ---------------- residual add + layernorm (row = 256) ----------------
__global__ __launch_bounds__(256) void add_ln(
    const float* __restrict__ x, const float* __restrict__ r,
    const float* __restrict__ g, const float* __restrict__ bta,
    float* __restrict__ out)
{
    __shared__ float warpsum[8];
    __shared__ float bcast;
    const int row = blockIdx.x, tid = threadIdx.x;
    const int lane = tid & 31, wid = tid >> 5;

    float v = x[(size_t)row * 256 + tid] + r[(size_t)row * 256 + tid];

    float s = v;
    #pragma unroll
    for (int o = 16; o > 0; o >>= 1) s += __shfl_xor_sync(0xFFFFFFFFu, s, o);
    if (lane == 0) warpsum[wid] = s;
    __syncthreads();
    if (tid == 0) {
        float tt = 0.f;
        #pragma unroll
        for (int i = 0; i < 8; i++) tt += warpsum[i];
        bcast = tt * (1.f / 256.f);
    }
    __syncthreads();
    float mean = bcast;
    float dcen = v - mean;

    float s2 = dcen * dcen;
    #pragma unroll
    for (int o = 16; o > 0; o >>= 1) s2 += __shfl_xor_sync(0xFFFFFFFFu, s2, o);
    if (lane == 0) warpsum[wid] = s2;
    __syncthreads();
    if (tid == 0) {
        float tt = 0.f;
        #pragma unroll
        for (int i = 0; i < 8; i++) tt += warpsum[i];
        bcast = tt * (1.f / 256.f);
    }
    __syncthreads();
    float var = bcast;

    out[(size_t)row * 256 + tid] = dcen * rsqrtf(var + 1e-5f) * g[tid] + bta[tid];
}

// ---------------- host orchestration ----------------
static inline void run_gemm(const float* A, const float* W, const float* bias,
                            void* C, int M, int N, int K, int mode)
{
    dim3 grid(N / 128, (M + 127) / 128);
    gemm_tf32<<<grid, 256, GEMM_SMEM>>>(A, W, bias, C, M, N, K, mode);
}

extern "C" void kernel_launch(void* const* d_in, const int* in_sizes, int n_in,
                              void* d_out, int out_size)
{
    const float* src     = (const float*)d_in[0];
    const float* pos     = (const float*)d_in[1];
    const float* vratios = (const float*)d_in[2];
    const float* W_value = (const float*)d_in[3];
    const float* b_value = (const float*)d_in[4];
    const float* W_off   = (const float*)d_in[5];
    const float* b_off   = (const float*)d_in[6];
    const float* W_attn  = (const float*)d_in[7];
    const float* b_attn  = (const float*)d_in[8];
    const float* W_out   = (const float*)d_in[9];
    const float* b_out   = (const float*)d_in[10];
    const float* ln1g    = (const float*)d_in[11];
    const float* ln1b    = (const float*)d_in[12];
    const float* W_ff1   = (const float*)d_in[13];
    const float* b_ff1   = (const float*)d_in[14];
    const float* W_ff2   = (const float*)d_in[15];
    const float* b_ff2   = (const float*)d_in[16];
    const float* ln2g    = (const float*)d_in[17];
    const float* ln2b    = (const float*)d_in[18];

    cudaFuncSetAttribute(gemm_tf32, cudaFuncAttributeMaxDynamicSharedMemorySize,
                         GEMM_SMEM);

    __half* pvalh;
    float *pq, *poff, *pattn, *pacc, *pa, *pff, *pcur, *pref;
    cudaGetSymbolAddress((void**)&pvalh, g_value_h);
    cudaGetSymbolAddress((void**)&pq,    g_q);
    cudaGetSymbolAddress((void**)&poff,  g_off);
    cudaGetSymbolAddress((void**)&pattn, g_attn);
    cudaGetSymbolAddress((void**)&pacc,  g_acc);
    cudaGetSymbolAddress((void**)&pa,    g_a);
    cudaGetSymbolAddress((void**)&pff,   g_ff);
    cudaGetSymbolAddress((void**)&pcur,  g_cur);
    cudaGetSymbolAddress((void**)&pref,  g_ref);

    const int nElem = T_TOT * DMODEL;
    const int M = T_TOT;

    compute_ref<<<(T_TOT + 255) / 256, 256>>>(vratios, pref);

    const float* cur = src;
    for (int i = 0; i < NLAYERS; i++) {
        const float* Wv  = W_value + (size_t)i * DMODEL * DMODEL;
        const float* bv  = b_value + (size_t)i * DMODEL;
        const float* Wof = W_off   + (size_t)i * DMODEL * DMODEL;
        const float* bof = b_off   + (size_t)i * DMODEL;
        const float* Wat = W_attn  + (size_t)i * DMODEL * 128;
        const float* bat = b_attn  + (size_t)i * 128;
        const float* Wo  = W_out   + (size_t)i * DMODEL * DMODEL;
        const float* bo  = b_out   + (size_t)i * DMODEL;
        const float* Wf1 = W_ff1   + (size_t)i * DMODEL * DFF;
        const float* bf1 = b_ff1   + (size_t)i * DFF;
        const float* Wf2 = W_ff2   + (size_t)i * DFF * DMODEL;
        const float* bf2 = b_ff2   + (size_t)i * DMODEL;

        // value projection -> fp16 buffer
        run_gemm(cur, Wv, bv, pvalh, M, DMODEL, DMODEL, 2);
        // q = cur + pos
        ew_add<<<(nElem + 255) / 256, 256>>>(cur, pos, pq, nElem);
        // offsets / attention logits
        run_gemm(pq, Wof, bof, poff, M, DMODEL, DMODEL, 0);
        run_gemm(pq, Wat, bat, pattn, M, 128, DMODEL, 0);
        // deformable sampling (softmax fused, fp16 value)
        msda_sample<<<T_TOT, 256>>>(pvalh, poff, pattn, pref, pacc);
        // output projection + residual LN
        run_gemm(pacc, Wo, bo, pa, M, DMODEL, DMODEL, 0);
        add_ln<<<T_TOT, 256>>>(cur, pa, ln1g + (size_t)i * DMODEL,
                               ln1b + (size_t)i * DMODEL, pcur);
        // FFN
        run_gemm(pcur, Wf1, bf1, pff, M, DFF, DMODEL, 1);
        run_gemm(pff, Wf2, bf2, pa, M, DMODEL, DFF, 0);
        float* dst = (i == NLAYERS - 1) ? (float*)d_out : pcur;
        add_ln<<<T_TOT, 256>>>(pcur, pa, ln2g + (size_t)i * DMODEL,
                               ln2b + (size_t)i * DMODEL, dst);
        cur = pcur;
    }
}